// round 2
// baseline (speedup 1.0000x reference)
#include <cuda_runtime.h>
#include <cuda_bf16.h>

#define N_NODES 50000
#define N_EDGES 800000
#define HID 128
#define NG 128
#define OUTD 10
#define EPS 1e-5f

// -------- device scratch (no allocations allowed) --------
__device__ int   d_is64;
__device__ int   d_deg[N_NODES];
__device__ int   d_rowptr[N_NODES + 1];
__device__ int   d_cursor[N_NODES];
__device__ int   d_col[N_EDGES];
__device__ __align__(16) float d_agg[N_NODES * HID];
__device__ __align__(16) float d_bufA[N_NODES * HID];
__device__ __align__(16) float d_bufB[N_NODES * HID];
__device__ __align__(16) float d_pooled[NG * HID];
__device__ float d_cnt[NG];

__device__ __forceinline__ float warp_sum(float v) {
    #pragma unroll
    for (int o = 16; o > 0; o >>= 1) v += __shfl_xor_sync(0xFFFFFFFFu, v, o);
    return v;
}

__device__ __forceinline__ int load_idx(const void* p, long long i) {
    if (d_is64) return (int)((const long long*)p)[i];
    return ((const int*)p)[i];
}

// -------- detect index dtype (int32 vs int64) --------
// If buffer is really int32, interpreting as int64 packs two random node ids;
// the chance all 256 such values land in [0, N_NODES) is ~(1/50000)^256.
__global__ void detect_kernel(const void* ei) {
    const long long* p = (const long long*)ei;
    int ok = 1;
    for (int i = 0; i < 256; i++) {
        long long v = p[i];
        if (v < 0 || v >= N_NODES) { ok = 0; break; }
    }
    d_is64 = ok;
}

// -------- zero per-call accumulators --------
__global__ void zero_kernel() {
    int i = blockIdx.x * blockDim.x + threadIdx.x;
    if (i < N_NODES) d_deg[i] = 0;
    if (i < NG * HID) d_pooled[i] = 0.0f;
    if (i < NG) d_cnt[i] = 0.0f;
}

// -------- CSR build: count, scan, fill --------
__global__ void count_kernel(const void* __restrict__ ei) {
    int e = blockIdx.x * blockDim.x + threadIdx.x;
    if (e < N_EDGES) {
        int dst = load_idx(ei, (long long)N_EDGES + e);
        atomicAdd(&d_deg[dst], 1);
    }
}

__global__ void scan_kernel() {
    __shared__ int sh[1024];
    __shared__ int offset;
    int tid = threadIdx.x;
    if (tid == 0) offset = 0;
    __syncthreads();
    for (int base = 0; base < N_NODES; base += 1024) {
        int v = (base + tid < N_NODES) ? d_deg[base + tid] : 0;
        sh[tid] = v;
        __syncthreads();
        #pragma unroll
        for (int s = 1; s < 1024; s <<= 1) {
            int t = (tid >= s) ? sh[tid - s] : 0;
            __syncthreads();
            sh[tid] += t;
            __syncthreads();
        }
        int excl = sh[tid] - v + offset;
        if (base + tid < N_NODES) {
            d_rowptr[base + tid] = excl;
            d_cursor[base + tid] = excl;
        }
        __syncthreads();
        if (tid == 1023) offset += sh[1023];
        __syncthreads();
    }
    if (tid == 0) d_rowptr[N_NODES] = offset;
}

__global__ void fill_kernel(const void* __restrict__ ei) {
    int e = blockIdx.x * blockDim.x + threadIdx.x;
    if (e < N_EDGES) {
        int src = load_idx(ei, e);
        int dst = load_idx(ei, (long long)N_EDGES + e);
        int pos = atomicAdd(&d_cursor[dst], 1);
        d_col[pos] = src;
    }
}

// -------- mean aggregation: one warp per node, gather from CSR --------
__global__ void aggregate_kernel(const float* __restrict__ xsrc) {
    const float* xp = xsrc ? xsrc : d_bufA;
    int gw = (blockIdx.x * blockDim.x + threadIdx.x) >> 5;
    int lane = threadIdx.x & 31;
    if (gw >= N_NODES) return;
    int b = d_rowptr[gw], e = d_rowptr[gw + 1];
    float4 acc = make_float4(0.f, 0.f, 0.f, 0.f);
    const float4* x4 = (const float4*)xp;
    for (int i = b; i < e; i++) {
        int s = __ldg(&d_col[i]);
        float4 v = __ldg(&x4[(size_t)s * 32 + lane]);
        acc.x += v.x; acc.y += v.y; acc.z += v.z; acc.w += v.w;
    }
    float inv = (e > b) ? 1.0f / (float)(e - b) : 0.0f;
    acc.x *= inv; acc.y *= inv; acc.z *= inv; acc.w *= inv;
    ((float4*)d_agg)[(size_t)gw * 32 + lane] = acc;
}

// -------- fused: x_new = relu(LN(agg@Wrel + brel + x@Wroot)) --------
// Block: 256 threads = 8 warps. Tile: 64 rows x 128 cols.
// Warp w computes rows [w*8, w*8+8); lane owns cols [lane*4, lane*4+4).
__global__ __launch_bounds__(256) void layer_kernel(
    const float* __restrict__ xin,      // nullptr -> d_bufA
    const float* __restrict__ Wrel,     // [128,128]
    const float* __restrict__ Wroot,    // [128,128]
    const float* __restrict__ brel,     // [128]
    const float* __restrict__ gam,      // [128]
    const float* __restrict__ bet,      // [128]
    int outsel)                          // 0 -> bufA, 1 -> bufB
{
    const float* xp = xin ? xin : d_bufA;
    float* outp = outsel ? d_bufB : d_bufA;

    __shared__ __align__(16) float As[32][65];
    __shared__ __align__(16) float Bs[32][128];

    int tid = threadIdx.x;
    int lane = tid & 31;
    int w = tid >> 5;
    int row0 = blockIdx.x * 64;

    float acc[8][4];
    #pragma unroll
    for (int r = 0; r < 8; r++)
        #pragma unroll
        for (int j = 0; j < 4; j++) acc[r][j] = 0.0f;

    #pragma unroll
    for (int pass = 0; pass < 2; pass++) {
        const float* A = pass ? xp : d_agg;
        const float* Wt = pass ? Wroot : Wrel;
        #pragma unroll
        for (int k0 = 0; k0 < 128; k0 += 32) {
            __syncthreads();
            // load A tile: warp w loads rows {w, w+8, ...}, col k0+lane
            #pragma unroll
            for (int i = 0; i < 8; i++) {
                int r = w + i * 8;
                int gr = row0 + r;
                As[lane][r] = (gr < N_NODES) ? A[(size_t)gr * HID + k0 + lane] : 0.0f;
            }
            // load B tile: 32x128 = 4096 elems, 16 per thread
            #pragma unroll
            for (int i = 0; i < 16; i++) {
                int idx = tid + i * 256;
                Bs[idx >> 7][idx & 127] = Wt[(size_t)(k0 + (idx >> 7)) * HID + (idx & 127)];
            }
            __syncthreads();
            #pragma unroll
            for (int kc = 0; kc < 32; kc++) {
                float4 bv = *(const float4*)&Bs[kc][lane * 4];
                #pragma unroll
                for (int r = 0; r < 8; r++) {
                    float a = As[kc][w * 8 + r];
                    acc[r][0] += a * bv.x;
                    acc[r][1] += a * bv.y;
                    acc[r][2] += a * bv.z;
                    acc[r][3] += a * bv.w;
                }
            }
        }
    }

    // epilogue: bias + LayerNorm + ReLU
    int c0 = lane * 4;
    float4 bb = *(const float4*)&brel[c0];
    float4 gg = *(const float4*)&gam[c0];
    float4 be = *(const float4*)&bet[c0];

    #pragma unroll
    for (int r = 0; r < 8; r++) {
        acc[r][0] += bb.x; acc[r][1] += bb.y; acc[r][2] += bb.z; acc[r][3] += bb.w;
        float s = acc[r][0] + acc[r][1] + acc[r][2] + acc[r][3];
        float mu = warp_sum(s) * (1.0f / 128.0f);
        float d0 = acc[r][0] - mu, d1 = acc[r][1] - mu, d2 = acc[r][2] - mu, d3 = acc[r][3] - mu;
        float sq = d0 * d0 + d1 * d1 + d2 * d2 + d3 * d3;
        float var = warp_sum(sq) * (1.0f / 128.0f);
        float rs = rsqrtf(var + EPS);
        float4 ov;
        ov.x = fmaxf(gg.x * d0 * rs + be.x, 0.0f);
        ov.y = fmaxf(gg.y * d1 * rs + be.y, 0.0f);
        ov.z = fmaxf(gg.z * d2 * rs + be.z, 0.0f);
        ov.w = fmaxf(gg.w * d3 * rs + be.w, 0.0f);
        int gr = row0 + w * 8 + r;
        if (gr < N_NODES)
            *(float4*)&outp[(size_t)gr * HID + c0] = ov;
    }
}

// -------- graph mean pooling (accumulate) --------
__global__ void pool_kernel(const void* __restrict__ batch) {
    int gw = (blockIdx.x * blockDim.x + threadIdx.x) >> 5;
    int lane = threadIdx.x & 31;
    if (gw >= N_NODES) return;
    int g = load_idx(batch, gw);
    float4 v = ((const float4*)d_bufB)[(size_t)gw * 32 + lane];
    float* p = &d_pooled[g * HID + lane * 4];
    atomicAdd(p + 0, v.x);
    atomicAdd(p + 1, v.y);
    atomicAdd(p + 2, v.z);
    atomicAdd(p + 3, v.w);
    if (lane == 0) atomicAdd(&d_cnt[g], 1.0f);
}

// -------- classifier: out[g][o] = (pooled[g]/cnt[g]) . Wc[:,o] + bc[o] --------
__global__ void cls_kernel(const float* __restrict__ Wc, const float* __restrict__ bc,
                           float* __restrict__ out) {
    int g = blockIdx.x;
    int tid = threadIdx.x;
    int o = tid >> 5;   // 10 warps -> 10 outputs
    int lane = tid & 31;
    if (o >= OUTD) return;
    float inv = 1.0f / fmaxf(d_cnt[g], 1.0f);
    float s = 0.0f;
    for (int k = lane; k < HID; k += 32)
        s += d_pooled[g * HID + k] * Wc[k * OUTD + o];
    s = warp_sum(s);
    if (lane == 0) out[g * OUTD + o] = s * inv + bc[o];
}

extern "C" void kernel_launch(void* const* d_in, const int* in_sizes, int n_in,
                              void* d_out, int out_size) {
    const float* x      = (const float*)d_in[0];
    const void*  ei     = d_in[1];
    const void*  batch  = d_in[2];
    const float* W_rel  = (const float*)d_in[3];
    const float* b_rel  = (const float*)d_in[4];
    const float* W_root = (const float*)d_in[5];
    const float* gamma  = (const float*)d_in[6];
    const float* beta   = (const float*)d_in[7];
    const float* Wc     = (const float*)d_in[8];
    const float* bc     = (const float*)d_in[9];
    float* out = (float*)d_out;

    detect_kernel<<<1, 1>>>(ei);
    zero_kernel<<<(N_NODES + 255) / 256, 256>>>();
    count_kernel<<<(N_EDGES + 255) / 256, 256>>>(ei);
    scan_kernel<<<1, 1024>>>();
    fill_kernel<<<(N_EDGES + 255) / 256, 256>>>(ei);

    // layer 0: reads input x, writes bufA
    aggregate_kernel<<<N_NODES / 8, 256>>>(x);
    layer_kernel<<<(N_NODES + 63) / 64, 256>>>(x, W_rel, W_root, b_rel, gamma, beta, 0);

    // layer 1: reads bufA, writes bufB
    aggregate_kernel<<<N_NODES / 8, 256>>>(nullptr);
    layer_kernel<<<(N_NODES + 63) / 64, 256>>>(nullptr, W_rel + HID * HID, W_root + HID * HID,
                                               b_rel + HID, gamma + HID, beta + HID, 1);

    pool_kernel<<<N_NODES / 8, 256>>>(batch);
    cls_kernel<<<NG, 320>>>(Wc, bc, out);
}

// round 3
// speedup vs baseline: 1.5559x; 1.5559x over previous
#include <cuda_runtime.h>
#include <cuda_bf16.h>

#define N_NODES 50000
#define N_EDGES 800000
#define HID 128
#define NG 128
#define OUTD 10
#define EPS 1e-5f
#define SCAN_BLOCKS 49   // 49*1024 >= 50000

// -------- device scratch (no allocations allowed) --------
__device__ int   d_is64;
__device__ int   d_deg[N_NODES];
__device__ int   d_rowptr[N_NODES + 1];
__device__ int   d_cursor[N_NODES];
__device__ int   d_bsum[SCAN_BLOCKS];
__device__ int   d_btop[SCAN_BLOCKS];
__device__ int   d_col[N_EDGES];
__device__ __align__(16) float d_agg[N_NODES * HID];
__device__ __align__(16) float d_bufA[N_NODES * HID];
__device__ __align__(16) float d_bufB[N_NODES * HID];
__device__ __align__(16) float d_pooled[NG * HID];
__device__ float d_cnt[NG];

__device__ __forceinline__ float warp_sum(float v) {
    #pragma unroll
    for (int o = 16; o > 0; o >>= 1) v += __shfl_xor_sync(0xFFFFFFFFu, v, o);
    return v;
}

__device__ __forceinline__ int load_idx(const void* p, long long i) {
    if (d_is64) return (int)((const long long*)p)[i];
    return ((const int*)p)[i];
}

// -------- detect index dtype (int32 vs int64), parallel --------
__global__ void detect_kernel(const void* ei) {
    __shared__ int bad;
    if (threadIdx.x == 0) bad = 0;
    __syncthreads();
    const long long* p = (const long long*)ei;
    long long v = p[threadIdx.x];
    if (v < 0 || v >= N_NODES) bad = 1;
    __syncthreads();
    if (threadIdx.x == 0) d_is64 = !bad;
}

// -------- zero per-call accumulators --------
__global__ void zero_kernel() {
    int i = blockIdx.x * blockDim.x + threadIdx.x;
    if (i < N_NODES) d_deg[i] = 0;
    if (i < NG * HID) d_pooled[i] = 0.0f;
    if (i < NG) d_cnt[i] = 0.0f;
}

// -------- CSR build: count, 3-phase scan, fill --------
__global__ void count_kernel(const void* __restrict__ ei) {
    int e = blockIdx.x * blockDim.x + threadIdx.x;
    if (e < N_EDGES) {
        int dst = load_idx(ei, (long long)N_EDGES + e);
        atomicAdd(&d_deg[dst], 1);
    }
}

__global__ void scan1_kernel() {
    __shared__ int sh[1024];
    int tid = threadIdx.x;
    int i = blockIdx.x * 1024 + tid;
    int v = (i < N_NODES) ? d_deg[i] : 0;
    sh[tid] = v;
    __syncthreads();
    #pragma unroll
    for (int s = 1; s < 1024; s <<= 1) {
        int t = (tid >= s) ? sh[tid - s] : 0;
        __syncthreads();
        sh[tid] += t;
        __syncthreads();
    }
    if (i < N_NODES) d_rowptr[i] = sh[tid] - v;  // block-local exclusive
    if (tid == 1023) d_bsum[blockIdx.x] = sh[1023];
}

__global__ void scan2_kernel() {
    __shared__ int sh[64];
    int tid = threadIdx.x;
    int v = (tid < SCAN_BLOCKS) ? d_bsum[tid] : 0;
    sh[tid] = v;
    __syncthreads();
    #pragma unroll
    for (int s = 1; s < 64; s <<= 1) {
        int t = (tid >= s) ? sh[tid - s] : 0;
        __syncthreads();
        sh[tid] += t;
        __syncthreads();
    }
    if (tid < SCAN_BLOCKS) d_btop[tid] = sh[tid] - v;
}

__global__ void scan3_kernel() {
    int i = blockIdx.x * blockDim.x + threadIdx.x;
    if (i < N_NODES) {
        int r = d_rowptr[i] + d_btop[i >> 10];
        d_rowptr[i] = r;
        d_cursor[i] = r;
    }
    if (i == 0) d_rowptr[N_NODES] = N_EDGES;
}

__global__ void fill_kernel(const void* __restrict__ ei) {
    int e = blockIdx.x * blockDim.x + threadIdx.x;
    if (e < N_EDGES) {
        int src = load_idx(ei, e);
        int dst = load_idx(ei, (long long)N_EDGES + e);
        int pos = atomicAdd(&d_cursor[dst], 1);
        d_col[pos] = src;
    }
}

// -------- mean aggregation: one warp per node, gather from CSR --------
__global__ void aggregate_kernel(const float* __restrict__ xsrc) {
    const float* xp = xsrc ? xsrc : d_bufA;
    int gw = (blockIdx.x * blockDim.x + threadIdx.x) >> 5;
    int lane = threadIdx.x & 31;
    if (gw >= N_NODES) return;
    int b = d_rowptr[gw], e = d_rowptr[gw + 1];
    float4 acc = make_float4(0.f, 0.f, 0.f, 0.f);
    const float4* x4 = (const float4*)xp;
    for (int i = b; i < e; i++) {
        int s = __ldg(&d_col[i]);
        float4 v = __ldg(&x4[(size_t)s * 32 + lane]);
        acc.x += v.x; acc.y += v.y; acc.z += v.z; acc.w += v.w;
    }
    float inv = (e > b) ? 1.0f / (float)(e - b) : 0.0f;
    acc.x *= inv; acc.y *= inv; acc.z *= inv; acc.w *= inv;
    ((float4*)d_agg)[(size_t)gw * 32 + lane] = acc;
}

// -------- fused: x_new = relu(LN(agg@Wrel + brel + x@Wroot)), optional pooling --------
// Block: 256 threads = 8 warps. Tile: 128 rows x 128 cols.
// Warp w owns rows [w*16, w*16+16); lane owns cols [lane*4, lane*4+4).
__global__ __launch_bounds__(256, 2) void layer_kernel(
    const float* __restrict__ xin,      // nullptr -> d_bufA
    const float* __restrict__ Wrel,     // [128,128]
    const float* __restrict__ Wroot,    // [128,128]
    const float* __restrict__ brel,     // [128]
    const float* __restrict__ gam,      // [128]
    const float* __restrict__ bet,      // [128]
    const void*  __restrict__ batch,    // only used when outsel==1
    int outsel)                          // 0 -> bufA, 1 -> bufB + pooling
{
    const float* xp = xin ? xin : d_bufA;
    float* outp = outsel ? d_bufB : d_bufA;

    __shared__ __align__(16) float As[32][132];  // [k][row], stride 132 for alignment
    __shared__ __align__(16) float Bs[32][128];  // [k][col]

    int tid = threadIdx.x;
    int lane = tid & 31;
    int w = tid >> 5;
    int w16 = w * 16;
    int row0 = blockIdx.x * 128;

    float acc[16][4];
    #pragma unroll
    for (int r = 0; r < 16; r++)
        #pragma unroll
        for (int j = 0; j < 4; j++) acc[r][j] = 0.0f;

    #pragma unroll
    for (int pass = 0; pass < 2; pass++) {
        const float* A = pass ? xp : d_agg;
        const float* Wt = pass ? Wroot : Wrel;
        #pragma unroll
        for (int k0 = 0; k0 < 128; k0 += 32) {
            __syncthreads();
            // A tile: 128 rows x 32 k, thread loads 16 elems (row=w+8i, k=lane)
            #pragma unroll
            for (int i = 0; i < 16; i++) {
                int r = w + i * 8;
                int gr = row0 + r;
                As[lane][r] = (gr < N_NODES) ? A[(size_t)gr * HID + k0 + lane] : 0.0f;
            }
            // B tile: 32 k x 128 cols = 4096 elems, 16 per thread
            #pragma unroll
            for (int i = 0; i < 16; i++) {
                int idx = tid + i * 256;
                Bs[idx >> 7][idx & 127] = Wt[(size_t)(k0 + (idx >> 7)) * HID + (idx & 127)];
            }
            __syncthreads();
            #pragma unroll
            for (int kc = 0; kc < 32; kc++) {
                float4 b4 = *(const float4*)&Bs[kc][lane * 4];
                float ar[16];
                *(float4*)&ar[0]  = *(const float4*)&As[kc][w16];
                *(float4*)&ar[4]  = *(const float4*)&As[kc][w16 + 4];
                *(float4*)&ar[8]  = *(const float4*)&As[kc][w16 + 8];
                *(float4*)&ar[12] = *(const float4*)&As[kc][w16 + 12];
                #pragma unroll
                for (int r = 0; r < 16; r++) {
                    acc[r][0] += ar[r] * b4.x;
                    acc[r][1] += ar[r] * b4.y;
                    acc[r][2] += ar[r] * b4.z;
                    acc[r][3] += ar[r] * b4.w;
                }
            }
        }
    }

    // epilogue: bias + LayerNorm + ReLU (+ fused graph pooling on last layer)
    int c0 = lane * 4;
    float4 bb = *(const float4*)&brel[c0];
    float4 gg = *(const float4*)&gam[c0];
    float4 be = *(const float4*)&bet[c0];

    int curg = -1, cnt_run = 0;
    float p0 = 0.f, p1 = 0.f, p2 = 0.f, p3 = 0.f;

    #pragma unroll
    for (int r = 0; r < 16; r++) {
        int gr = row0 + w16 + r;
        if (gr >= N_NODES) break;  // uniform per warp (rows are warp-contiguous)
        float v0 = acc[r][0] + bb.x, v1 = acc[r][1] + bb.y;
        float v2 = acc[r][2] + bb.z, v3 = acc[r][3] + bb.w;
        float mu = warp_sum(v0 + v1 + v2 + v3) * (1.0f / 128.0f);
        float d0 = v0 - mu, d1 = v1 - mu, d2 = v2 - mu, d3 = v3 - mu;
        float var = warp_sum(d0 * d0 + d1 * d1 + d2 * d2 + d3 * d3) * (1.0f / 128.0f);
        float rs = rsqrtf(var + EPS);
        float4 ov;
        ov.x = fmaxf(gg.x * d0 * rs + be.x, 0.0f);
        ov.y = fmaxf(gg.y * d1 * rs + be.y, 0.0f);
        ov.z = fmaxf(gg.z * d2 * rs + be.z, 0.0f);
        ov.w = fmaxf(gg.w * d3 * rs + be.w, 0.0f);
        *(float4*)&outp[(size_t)gr * HID + c0] = ov;

        if (outsel) {  // run-length pooled accumulation (batch is sorted)
            int g = load_idx(batch, gr);
            if (g != curg) {
                if (curg >= 0) {
                    float* pp = &d_pooled[curg * HID + c0];
                    atomicAdd(pp + 0, p0); atomicAdd(pp + 1, p1);
                    atomicAdd(pp + 2, p2); atomicAdd(pp + 3, p3);
                    if (lane == 0) atomicAdd(&d_cnt[curg], (float)cnt_run);
                }
                curg = g; cnt_run = 1;
                p0 = ov.x; p1 = ov.y; p2 = ov.z; p3 = ov.w;
            } else {
                p0 += ov.x; p1 += ov.y; p2 += ov.z; p3 += ov.w;
                cnt_run++;
            }
        }
    }
    if (outsel && curg >= 0) {
        float* pp = &d_pooled[curg * HID + c0];
        atomicAdd(pp + 0, p0); atomicAdd(pp + 1, p1);
        atomicAdd(pp + 2, p2); atomicAdd(pp + 3, p3);
        if (lane == 0) atomicAdd(&d_cnt[curg], (float)cnt_run);
    }
}

// -------- classifier: out[g][o] = (pooled[g]/cnt[g]) . Wc[:,o] + bc[o] --------
__global__ void cls_kernel(const float* __restrict__ Wc, const float* __restrict__ bc,
                           float* __restrict__ out) {
    int g = blockIdx.x;
    int tid = threadIdx.x;
    int o = tid >> 5;   // 10 warps -> 10 outputs
    int lane = tid & 31;
    if (o >= OUTD) return;
    float inv = 1.0f / fmaxf(d_cnt[g], 1.0f);
    float s = 0.0f;
    for (int k = lane; k < HID; k += 32)
        s += d_pooled[g * HID + k] * Wc[k * OUTD + o];
    s = warp_sum(s);
    if (lane == 0) out[g * OUTD + o] = s * inv + bc[o];
}

extern "C" void kernel_launch(void* const* d_in, const int* in_sizes, int n_in,
                              void* d_out, int out_size) {
    const float* x      = (const float*)d_in[0];
    const void*  ei     = d_in[1];
    const void*  batch  = d_in[2];
    const float* W_rel  = (const float*)d_in[3];
    const float* b_rel  = (const float*)d_in[4];
    const float* W_root = (const float*)d_in[5];
    const float* gamma  = (const float*)d_in[6];
    const float* beta   = (const float*)d_in[7];
    const float* Wc     = (const float*)d_in[8];
    const float* bc     = (const float*)d_in[9];
    float* out = (float*)d_out;

    detect_kernel<<<1, 256>>>(ei);
    zero_kernel<<<(N_NODES + 255) / 256, 256>>>();
    count_kernel<<<(N_EDGES + 255) / 256, 256>>>(ei);
    scan1_kernel<<<SCAN_BLOCKS, 1024>>>();
    scan2_kernel<<<1, 64>>>();
    scan3_kernel<<<SCAN_BLOCKS, 1024>>>();
    fill_kernel<<<(N_EDGES + 255) / 256, 256>>>(ei);

    // layer 0: reads input x, writes bufA
    aggregate_kernel<<<N_NODES / 8, 256>>>(x);
    layer_kernel<<<(N_NODES + 127) / 128, 256>>>(x, W_rel, W_root, b_rel, gamma, beta,
                                                 batch, 0);

    // layer 1: reads bufA, writes bufB + fused pooling
    aggregate_kernel<<<N_NODES / 8, 256>>>(nullptr);
    layer_kernel<<<(N_NODES + 127) / 128, 256>>>(nullptr, W_rel + HID * HID,
                                                 W_root + HID * HID, b_rel + HID,
                                                 gamma + HID, beta + HID, batch, 1);

    cls_kernel<<<NG, 320>>>(Wc, bc, out);
}

// round 10
// speedup vs baseline: 3.3024x; 2.1225x over previous
#include <cuda_runtime.h>
#include <cuda_bf16.h>
#include <cstdint>

#define N_NODES 50000
#define N_EDGES 800000
#define HID 128
#define NG 128
#define OUTD 10
#define EPS 1e-5f
#define SCAN_BLOCKS 49

#if defined(__CUDA_ARCH_FEAT_SM103_ALL) || defined(__CUDA_ARCH_FEAT_SM100_ALL) || \
    (defined(__CUDA_ARCH_SPECIFIC__))
#define HAS_TCGEN05 1
#else
#define HAS_TCGEN05 0
#endif

// ---- layer_tc smem layout (byte offsets from 1024-aligned base) ----
#define OFF_TMEM 0
#define OFF_MBAR0 8
#define OFF_MBAR1 16
#define OFF_BIAS 64
#define OFF_GAM  576
#define OFF_BET  1088
#define OFF_WH   2048                  // weight hi tile, blocked-atom, 32KB
#define OFF_WL   (OFF_WH + 32768)      // weight lo tile, 32KB
#define SMEM_USED (OFF_WH + 67584)     // staging (128*33*16B) overlays WH/WL
#define SMEM_TOTAL (SMEM_USED + 1024)  // + alignment slack
// kind::f16 idesc, N=64: proven encodings only (test_mma: M=128 cg1 f16;
// test_2cta: (N/8)<<17 with N=64). 0x8000000|0x100000|0x490 = 0x8100490
#define BF16_IDESC_N64 0x8100490u
#define TMEM_COLS 256
#define TM_D  0
#define TM_AH 128
#define TM_AL 192

// -------- device scratch --------
__device__ int   d_is64;
__device__ int   d_deg[N_NODES];
__device__ int   d_rowptr[N_NODES + 1];
__device__ int   d_cursor[N_NODES];
__device__ int   d_bsum[SCAN_BLOCKS];
__device__ int   d_btop[SCAN_BLOCKS];
__device__ int   d_col[N_EDGES];
__device__ __align__(16) float d_wt[4 * HID * HID];   // transposed weights [N][K]
__device__ __align__(16) float d_agg[N_NODES * HID];
__device__ __align__(16) float d_bufA[N_NODES * HID];
__device__ __align__(16) float d_bufB[N_NODES * HID];
__device__ __align__(16) float d_pooled[NG * HID];
__device__ float d_cnt[NG];

__device__ __forceinline__ float warp_sum(float v) {
    #pragma unroll
    for (int o = 16; o > 0; o >>= 1) v += __shfl_xor_sync(0xFFFFFFFFu, v, o);
    return v;
}
__device__ __forceinline__ int load_idx(const void* p, long long i) {
    if (d_is64) return (int)((const long long*)p)[i];
    return ((const int*)p)[i];
}
__device__ __forceinline__ uint32_t smem_u32(const void* p) {
    uint32_t a;
    asm("{ .reg .u64 t; cvta.to.shared.u64 t, %1; cvt.u32.u64 %0, t; }" : "=r"(a) : "l"(p));
    return a;
}
__device__ __forceinline__ uint64_t make_desc(uint32_t addr) {
    const uint64_t base = (uint64_t(2) << 61) | (uint64_t(1) << 46) |
                          (uint64_t(64) << 32) | (uint64_t(1) << 16);
    return base | ((uint64_t)(addr >> 4) & 0x3FFF);
}

#if HAS_TCGEN05
__device__ __forceinline__ uint32_t elect_one() {
    uint32_t r;
    asm volatile("{\n\t.reg .pred p;\n\telect.sync _|p, 0xFFFFFFFF;\n\tselp.b32 %0, 1, 0, p;\n\t}" : "=r"(r));
    return r;
}
// TS-form f16 MMA, verbatim from ptx_helpers TCGEN05_MMA_F16 (proven in test_mma_iter)
#define TC_MMA_F16_TS(d_tmem, a_tmem, b_desc, idesc, enable_d) do { \
    uint32_t _enable = (enable_d) ? 1 : 0; \
    uint32_t _zero = 0; \
    asm volatile( \
        "{\n\t" \
        ".reg .pred p;\n\t" \
        "setp.ne.u32 p, %6, 0;\n\t" \
        "tcgen05.mma.cta_group::1.kind::f16 [%0], [%1], %2, %3, " \
        "{%4, %4, %4, %4}, p;\n\t" \
        "}" \
        :: "r"(d_tmem), "r"(a_tmem), "l"(b_desc), "r"(idesc), \
           "r"(_zero), "r"(_zero), "r"(_enable) \
        : "memory"); \
} while (0)
#define TC_ALLOC(slot, n)   asm volatile("tcgen05.alloc.cta_group::1.sync.aligned.shared::cta.b32 [%0], %1;" :: "r"(slot), "r"((uint32_t)(n)) : "memory")
#define TC_DEALLOC(t, n)    asm volatile("tcgen05.dealloc.cta_group::1.sync.aligned.b32 %0, %1;" :: "r"(t), "r"((uint32_t)(n)))
#define TC_COMMIT(mb)       asm volatile("tcgen05.commit.cta_group::1.mbarrier::arrive::one.shared::cluster.b64 [%0];" :: "r"(mb) : "memory")
#define TC_WAIT_LD()        asm volatile("tcgen05.wait::ld.sync.aligned;" ::: "memory")
#define TC_WAIT_ST()        asm volatile("tcgen05.wait::st.sync.aligned;" ::: "memory")
#define TC_FENCE_AFTER()    asm volatile("tcgen05.fence::after_thread_sync;" ::: "memory")
#define TC_FENCE_BEFORE()   asm volatile("tcgen05.fence::before_thread_sync;" ::: "memory")
#define MBAR_INIT(mb, c)    asm volatile("mbarrier.init.shared.b64 [%0], %1;" :: "r"(mb), "r"((uint32_t)(c)) : "memory")
#define MBAR_INVAL(mb)      asm volatile("mbarrier.inval.shared.b64 [%0];" :: "r"(mb) : "memory")
#define MBAR_WAIT(mb, ph) do { \
    uint32_t _m = (mb), _p = (ph), _d; \
    asm volatile("{\n\t.reg .pred p;\n\tmbarrier.try_wait.parity.acquire.cta.shared::cta.b64 p, [%1], %2;\n\tselp.b32 %0, 1, 0, p;\n\t}" \
        : "=r"(_d) : "r"(_m), "r"(_p) : "memory"); \
    if (!_d) { \
        asm volatile("{\n\t.reg .pred P1;\n\tWL_%=:\n\tmbarrier.try_wait.parity.acquire.cta.shared::cta.b64 P1, [%0], %1, 0x989680;\n\t@P1 bra.uni WD_%=;\n\tbra.uni WL_%=;\n\tWD_%=:\n\t}" \
            :: "r"(_m), "r"(_p) : "memory"); \
    } \
} while (0)

#define TC_ST_X16(tmem_addr, r) \
    asm volatile( \
        "tcgen05.st.sync.aligned.32x32b.x16.b32 [%0], " \
        "{%1, %2, %3, %4, %5, %6, %7, %8, " \
        " %9, %10, %11, %12, %13, %14, %15, %16};" \
        :: "r"(tmem_addr), \
           "r"((r)[0]),  "r"((r)[1]),  "r"((r)[2]),  "r"((r)[3]), \
           "r"((r)[4]),  "r"((r)[5]),  "r"((r)[6]),  "r"((r)[7]), \
           "r"((r)[8]),  "r"((r)[9]),  "r"((r)[10]), "r"((r)[11]), \
           "r"((r)[12]), "r"((r)[13]), "r"((r)[14]), "r"((r)[15]) \
        : "memory")

#define TC_LD_X32(r, addr) \
    asm volatile( \
        "tcgen05.ld.sync.aligned.32x32b.x32.b32 " \
        "{%0, %1, %2, %3, %4, %5, %6, %7, %8, %9, %10, %11, %12, %13, %14, %15, " \
        " %16, %17, %18, %19, %20, %21, %22, %23, %24, %25, %26, %27, %28, %29, %30, %31}, [%32];" \
        : "=r"((r)[0]), "=r"((r)[1]), "=r"((r)[2]), "=r"((r)[3]), \
          "=r"((r)[4]), "=r"((r)[5]), "=r"((r)[6]), "=r"((r)[7]), \
          "=r"((r)[8]), "=r"((r)[9]), "=r"((r)[10]), "=r"((r)[11]), \
          "=r"((r)[12]), "=r"((r)[13]), "=r"((r)[14]), "=r"((r)[15]), \
          "=r"((r)[16]), "=r"((r)[17]), "=r"((r)[18]), "=r"((r)[19]), \
          "=r"((r)[20]), "=r"((r)[21]), "=r"((r)[22]), "=r"((r)[23]), \
          "=r"((r)[24]), "=r"((r)[25]), "=r"((r)[26]), "=r"((r)[27]), \
          "=r"((r)[28]), "=r"((r)[29]), "=r"((r)[30]), "=r"((r)[31]) \
        : "r"(addr))
#endif  // HAS_TCGEN05

// -------- detect index dtype --------
__global__ void detect_kernel(const void* ei) {
    __shared__ int bad;
    if (threadIdx.x == 0) bad = 0;
    __syncthreads();
    long long v = ((const long long*)ei)[threadIdx.x];
    if (v < 0 || v >= N_NODES) bad = 1;
    __syncthreads();
    if (threadIdx.x == 0) d_is64 = !bad;
}

__global__ void zero_kernel() {
    int i = blockIdx.x * blockDim.x + threadIdx.x;
    if (i < N_NODES) d_deg[i] = 0;
    if (i < NG * HID) d_pooled[i] = 0.0f;
    if (i < NG) d_cnt[i] = 0.0f;
}

// -------- transpose weights: d_wt[m][n][k] = W_m[k][n] --------
__global__ void transpose_w(const float* __restrict__ W_rel, const float* __restrict__ W_root) {
    int idx = blockIdx.x * 256 + threadIdx.x;        // 0..65535
    int m = idx >> 14, e = idx & 16383;
    int n = e >> 7, k = e & 127;
    const float* src = (m & 1) ? (W_root + (m >> 1) * HID * HID)
                               : (W_rel  + (m >> 1) * HID * HID);
    d_wt[m * HID * HID + n * HID + k] = src[k * HID + n];
}

// -------- CSR build --------
__global__ void count_kernel(const void* __restrict__ ei) {
    int e = blockIdx.x * blockDim.x + threadIdx.x;
    if (e < N_EDGES) atomicAdd(&d_deg[load_idx(ei, (long long)N_EDGES + e)], 1);
}
__global__ void scan1_kernel() {
    __shared__ int sh[1024];
    int tid = threadIdx.x, i = blockIdx.x * 1024 + tid;
    int v = (i < N_NODES) ? d_deg[i] : 0;
    sh[tid] = v; __syncthreads();
    #pragma unroll
    for (int s = 1; s < 1024; s <<= 1) {
        int t = (tid >= s) ? sh[tid - s] : 0;
        __syncthreads(); sh[tid] += t; __syncthreads();
    }
    if (i < N_NODES) d_rowptr[i] = sh[tid] - v;
    if (tid == 1023) d_bsum[blockIdx.x] = sh[1023];
}
__global__ void scan2_kernel() {
    __shared__ int sh[64];
    int tid = threadIdx.x;
    int v = (tid < SCAN_BLOCKS) ? d_bsum[tid] : 0;
    sh[tid] = v; __syncthreads();
    #pragma unroll
    for (int s = 1; s < 64; s <<= 1) {
        int t = (tid >= s) ? sh[tid - s] : 0;
        __syncthreads(); sh[tid] += t; __syncthreads();
    }
    if (tid < SCAN_BLOCKS) d_btop[tid] = sh[tid] - v;
}
__global__ void scan3_kernel() {
    int i = blockIdx.x * blockDim.x + threadIdx.x;
    if (i < N_NODES) {
        int r = d_rowptr[i] + d_btop[i >> 10];
        d_rowptr[i] = r; d_cursor[i] = r;
    }
    if (i == 0) d_rowptr[N_NODES] = N_EDGES;
}
__global__ void fill_kernel(const void* __restrict__ ei) {
    int e = blockIdx.x * blockDim.x + threadIdx.x;
    if (e < N_EDGES) {
        int src = load_idx(ei, e);
        int dst = load_idx(ei, (long long)N_EDGES + e);
        d_col[atomicAdd(&d_cursor[dst], 1)] = src;
    }
}

// -------- mean aggregation --------
__global__ void aggregate_kernel(const float* __restrict__ xsrc) {
    const float* xp = xsrc ? xsrc : d_bufA;
    int gw = (blockIdx.x * blockDim.x + threadIdx.x) >> 5;
    int lane = threadIdx.x & 31;
    if (gw >= N_NODES) return;
    int b = d_rowptr[gw], e = d_rowptr[gw + 1];
    float4 acc = make_float4(0.f, 0.f, 0.f, 0.f);
    const float4* x4 = (const float4*)xp;
    for (int i = b; i < e; i++) {
        int s = __ldg(&d_col[i]);
        float4 v = __ldg(&x4[(size_t)s * 32 + lane]);
        acc.x += v.x; acc.y += v.y; acc.z += v.z; acc.w += v.w;
    }
    float inv = (e > b) ? 1.0f / (float)(e - b) : 0.0f;
    acc.x *= inv; acc.y *= inv; acc.z *= inv; acc.w *= inv;
    ((float4*)d_agg)[(size_t)gw * 32 + lane] = acc;
}

#if HAS_TCGEN05
// -------- split f32 -> hi/lo bf16x2 words --------
__device__ __forceinline__ void split4(float4 v, uint32_t* hw, uint32_t* lw) {
    __nv_bfloat16 h0 = __float2bfloat16(v.x), h1 = __float2bfloat16(v.y);
    __nv_bfloat16 h2 = __float2bfloat16(v.z), h3 = __float2bfloat16(v.w);
    __nv_bfloat16 l0 = __float2bfloat16(v.x - __bfloat162float(h0));
    __nv_bfloat16 l1 = __float2bfloat16(v.y - __bfloat162float(h1));
    __nv_bfloat16 l2 = __float2bfloat16(v.z - __bfloat162float(h2));
    __nv_bfloat16 l3 = __float2bfloat16(v.w - __bfloat162float(h3));
    __nv_bfloat162 hp0 = __halves2bfloat162(h0, h1), hp1 = __halves2bfloat162(h2, h3);
    __nv_bfloat162 lp0 = __halves2bfloat162(l0, l1), lp1 = __halves2bfloat162(l2, l3);
    hw[0] = *(uint32_t*)&hp0; hw[1] = *(uint32_t*)&hp1;
    lw[0] = *(uint32_t*)&lp0; lw[1] = *(uint32_t*)&lp1;
}

// -------- store A (128 rows x 128 f32) to TMEM as hi/lo bf16x2 (TS mode) --------
__device__ __forceinline__ void store_A_tmem(uint32_t tmem, const float* gsrc, int row0) {
    int tid = threadIdx.x;
    if (tid >= 128) return;
    int gr = row0 + tid;
    bool ok = gr < N_NODES;
    const float4* rp = (const float4*)gsrc + (size_t)gr * 32;
    uint32_t woff = ((uint32_t)(tid >> 5)) << 21;
    #pragma unroll
    for (int ch = 0; ch < 4; ch++) {      // 16 TMEM cols (= 32 f32) per chunk
        uint32_t hw[16], lw[16];
        #pragma unroll
        for (int q = 0; q < 8; q++) {
            float4 v = ok ? __ldg(rp + ch * 8 + q) : make_float4(0.f, 0.f, 0.f, 0.f);
            split4(v, hw + q * 2, lw + q * 2);
        }
        TC_ST_X16(tmem + TM_AH + ch * 16 + woff, hw);
        TC_ST_X16(tmem + TM_AL + ch * 16 + woff, lw);
    }
    TC_WAIT_ST();
}

// -------- store weights [N=128][K=128] f32 -> hi/lo bf16 blocked-atom SMEM --------
// atom = 8 rows x 64 bf16 (1024B); tiling (16 atom-rows, 2 atom-cols), stride (1,16).
__device__ __forceinline__ void store_W_smem(char* base, const float* wt) {
    int tid = threadIdx.x;
    #pragma unroll
    for (int i = 0; i < 8; i++) {
        int chunk = tid + i * 256;        // 0..2047, each = 8 bf16 (16B)
        int n = chunk >> 4, c8 = chunk & 15;
        const float4* p = (const float4*)(wt + n * HID + c8 * 8);
        float4 v0 = __ldg(p), v1 = __ldg(p + 1);
        uint32_t hw[4], lw[4];
        split4(v0, hw, lw);
        split4(v1, hw + 2, lw + 2);
        int atom_row = n >> 3, inner_row = n & 7;
        int atom_col = c8 >> 3, ic8 = c8 & 7;
        uint32_t b = (uint32_t)((atom_row + atom_col * 16) * 1024 + inner_row * 128 + ic8 * 16);
        b ^= (b >> 3) & 0x70;             // SW128
        *(uint4*)(base + OFF_WH + b) = make_uint4(hw[0], hw[1], hw[2], hw[3]);
        *(uint4*)(base + OFF_WL + b) = make_uint4(lw[0], lw[1], lw[2], lw[3]);
    }
}

// 48 MMAs: 2 N-halves x products (Ah,Bh),(Ah,Bl),(Al,Bh) x 8 K-steps (K=16 each).
// a step: +8 TMEM cols; b step: atom_col (s>>2)*1024 units + (s&3)*2 units;
// N-half h: +h*8 atoms = +h*512 units, D cols +h*64.
__device__ __forceinline__ void mma_gemm_ts(uint32_t tmem, uint32_t sbase, bool first) {
    uint64_t bh = make_desc(sbase + OFF_WH);
    uint64_t bl = make_desc(sbase + OFF_WL);
    uint32_t ah = tmem + TM_AH, al = tmem + TM_AL;
    uint32_t apair[3] = {ah, ah, al};
    uint64_t bpair[3] = {bh, bl, bh};
    #pragma unroll
    for (int h = 0; h < 2; h++) {
        #pragma unroll
        for (int p = 0; p < 3; p++) {
            #pragma unroll
            for (int s = 0; s < 8; s++) {
                uint64_t bd = bpair[p] + (uint64_t)(h * 512 + (s >> 2) * 1024 + (s & 3) * 2);
                TC_MMA_F16_TS(tmem + TM_D + h * 64, apair[p] + s * 8, bd, BF16_IDESC_N64,
                              !(first && p == 0 && s == 0));
            }
        }
    }
}
#endif

// -------- layer: out = relu(LN(agg@Wrel + brel + x@Wroot)) --------
// NOTE: weights come from the d_wt device symbol, selected by `layer` INSIDE
// device code. Passing d_wt as a host-side kernel argument passes the HOST
// shadow address, which GB300's ATS dereferences to zeros (the rounds-4..9 bug).
__global__ void __launch_bounds__(256, 1) __cluster_dims__(1, 1, 1) layer_tc(
    const float* __restrict__ xin,        // nullptr -> d_bufA
    const float* __restrict__ brel,
    const float* __restrict__ gam,
    const float* __restrict__ bet,
    int layer, int outsel)
{
    extern __shared__ char smem_raw[];
    const float* xp = xin ? xin : d_bufA;
    float* outp = outsel ? d_bufB : d_bufA;
    const float* wtrel  = d_wt + (2 * layer)     * HID * HID;  // device-side symbol
    const float* wtroot = d_wt + (2 * layer + 1) * HID * HID;
    int tid = threadIdx.x;
    int row0 = blockIdx.x * 128;

#if HAS_TCGEN05
    uint32_t sraw = smem_u32(smem_raw);
    uint32_t sbase = (sraw + 1023u) & ~1023u;   // SW128 tiles need 1024B alignment
    char* base = smem_raw + (sbase - sraw);
    int wid = tid >> 5;

    float* sBias = (float*)(base + OFF_BIAS);
    float* sGam  = (float*)(base + OFF_GAM);
    float* sBet  = (float*)(base + OFF_BET);
    if (tid < 128) { sBias[tid] = brel[tid]; sGam[tid] = gam[tid]; sBet[tid] = bet[tid]; }

    // alloc by warp 0 ONLY; no relinquish (hi-wid-first arbiter would order a
    // relinquish from warps 1-7 before the alloc -> illegal).
    if (wid == 0) { TC_ALLOC(sbase + OFF_TMEM, TMEM_COLS); }
    if (tid == 0) { MBAR_INIT(sbase + OFF_MBAR0, 1); MBAR_INIT(sbase + OFF_MBAR1, 1); }
    __syncthreads();
    uint32_t tmem;
    asm volatile("ld.shared.b32 %0, [%1];" : "=r"(tmem) : "r"(sbase + OFF_TMEM));

    // ---- GEMM 1: D = agg @ Wrel^T (A in TMEM, B in SMEM; proven TS path) ----
    store_A_tmem(tmem, d_agg, row0);
    store_W_smem(base, wtrel);
    TC_FENCE_BEFORE();
    __syncthreads();
    if (wid == 0) {
        TC_FENCE_AFTER();
        if (elect_one()) {
            mma_gemm_ts(tmem, sbase, true);
            TC_COMMIT(sbase + OFF_MBAR0);
        }
    }
    MBAR_WAIT(sbase + OFF_MBAR0, 0);

    // ---- GEMM 2: D += x @ Wroot^T ----
    store_A_tmem(tmem, xp, row0);
    store_W_smem(base, wtroot);
    TC_FENCE_BEFORE();
    __syncthreads();
    if (wid == 0) {
        TC_FENCE_AFTER();
        if (elect_one()) {
            mma_gemm_ts(tmem, sbase, false);
            TC_COMMIT(sbase + OFF_MBAR1);
        }
    }
    MBAR_WAIT(sbase + OFF_MBAR1, 0);
    TC_FENCE_AFTER();

    // ---- epilogue: warps 0-3, thread = row; LN in-register, stage to smem ----
    float* stg = (float*)(base + OFF_WH);   // stride 132 floats (33 float4)
    if (tid < 128) {
        uint32_t dr[128];
        TC_LD_X32(dr +  0, tmem + TM_D +  0);
        TC_LD_X32(dr + 32, tmem + TM_D + 32);
        TC_LD_X32(dr + 64, tmem + TM_D + 64);
        TC_LD_X32(dr + 96, tmem + TM_D + 96);
        TC_WAIT_LD();
        TC_FENCE_BEFORE();

        float sum = 0.0f;
        #pragma unroll
        for (int c = 0; c < 128; c++) {
            float v = __uint_as_float(dr[c]) + sBias[c];
            dr[c] = __float_as_uint(v);
            sum += v;
        }
        float mu = sum * (1.0f / 128.0f);
        float sq = 0.0f;
        #pragma unroll
        for (int c = 0; c < 128; c++) {
            float d = __uint_as_float(dr[c]) - mu;
            sq += d * d;
        }
        float rs = rsqrtf(sq * (1.0f / 128.0f) + EPS);
        int r = tid;
        #pragma unroll
        for (int c4 = 0; c4 < 32; c4++) {
            float4 ov;
            float* o = (float*)&ov;
            #pragma unroll
            for (int j = 0; j < 4; j++) {
                int c = c4 * 4 + j;
                float d = __uint_as_float(dr[c]) - mu;
                o[j] = fmaxf(sGam[c] * d * rs + sBet[c], 0.0f);
            }
            ((float4*)stg)[r * 33 + c4] = ov;
        }
    }
    __syncthreads();

    #pragma unroll
    for (int i = 0; i < 16; i++) {
        int idx = tid + i * 256;
        int r = idx >> 5, c4 = idx & 31;
        int gr = row0 + r;
        if (gr < N_NODES)
            ((float4*)outp)[(size_t)gr * 32 + c4] = ((float4*)stg)[r * 33 + c4];
    }
    __syncthreads();

    if (tid == 0) { MBAR_INVAL(sbase + OFF_MBAR0); MBAR_INVAL(sbase + OFF_MBAR1); }
    __syncthreads();
    if (wid == 0) { TC_DEALLOC(tmem, TMEM_COLS); }

#else
    // ---- SIMT fallback (generic sm_103 pass only; sm_103a cubin wins at runtime) ----
    char* smem = smem_raw;
    float (*As)[132] = (float(*)[132])(smem);                 // [k][row]
    float (*Bs)[128] = (float(*)[128])(smem + 32 * 132 * 4);  // [k][col]
    int lane = tid & 31;
    int w = tid >> 5;
    int w16 = w * 16;

    float acc[16][4];
    #pragma unroll
    for (int r = 0; r < 16; r++)
        #pragma unroll
        for (int j = 0; j < 4; j++) acc[r][j] = 0.0f;

    #pragma unroll
    for (int pass = 0; pass < 2; pass++) {
        const float* A = pass ? xp : d_agg;
        const float* Wt = pass ? wtroot : wtrel;    // [N][K] transposed
        #pragma unroll
        for (int k0 = 0; k0 < 128; k0 += 32) {
            __syncthreads();
            #pragma unroll
            for (int i = 0; i < 16; i++) {
                int r = w + i * 8;
                int gr = row0 + r;
                As[lane][r] = (gr < N_NODES) ? A[(size_t)gr * HID + k0 + lane] : 0.0f;
            }
            #pragma unroll
            for (int i = 0; i < 16; i++) {
                int idx = tid + i * 256;
                int kk = idx >> 7, nn = idx & 127;
                Bs[kk][nn] = Wt[(size_t)nn * HID + k0 + kk];
            }
            __syncthreads();
            #pragma unroll
            for (int kc = 0; kc < 32; kc++) {
                float4 b4 = *(const float4*)&Bs[kc][lane * 4];
                float ar[16];
                *(float4*)&ar[0]  = *(const float4*)&As[kc][w16];
                *(float4*)&ar[4]  = *(const float4*)&As[kc][w16 + 4];
                *(float4*)&ar[8]  = *(const float4*)&As[kc][w16 + 8];
                *(float4*)&ar[12] = *(const float4*)&As[kc][w16 + 12];
                #pragma unroll
                for (int r = 0; r < 16; r++) {
                    acc[r][0] += ar[r] * b4.x;
                    acc[r][1] += ar[r] * b4.y;
                    acc[r][2] += ar[r] * b4.z;
                    acc[r][3] += ar[r] * b4.w;
                }
            }
        }
    }

    int c0 = lane * 4;
    float4 bb = *(const float4*)&brel[c0];
    float4 gg = *(const float4*)&gam[c0];
    float4 be = *(const float4*)&bet[c0];
    #pragma unroll
    for (int r = 0; r < 16; r++) {
        int gr = row0 + w16 + r;
        if (gr >= N_NODES) break;
        float v0 = acc[r][0] + bb.x, v1 = acc[r][1] + bb.y;
        float v2 = acc[r][2] + bb.z, v3 = acc[r][3] + bb.w;
        float mu = warp_sum(v0 + v1 + v2 + v3) * (1.0f / 128.0f);
        float d0 = v0 - mu, d1 = v1 - mu, d2 = v2 - mu, d3 = v3 - mu;
        float var = warp_sum(d0 * d0 + d1 * d1 + d2 * d2 + d3 * d3) * (1.0f / 128.0f);
        float rs = rsqrtf(var + EPS);
        float4 ov;
        ov.x = fmaxf(gg.x * d0 * rs + be.x, 0.0f);
        ov.y = fmaxf(gg.y * d1 * rs + be.y, 0.0f);
        ov.z = fmaxf(gg.z * d2 * rs + be.z, 0.0f);
        ov.w = fmaxf(gg.w * d3 * rs + be.w, 0.0f);
        *(float4*)&outp[(size_t)gr * HID + c0] = ov;
    }
#endif
}

// -------- graph mean pooling: warp handles 32 consecutive rows, run-length --------
__global__ void pool_kernel(const void* __restrict__ batch) {
    int warp = (blockIdx.x * blockDim.x + threadIdx.x) >> 5;
    int lane = threadIdx.x & 31;
    int r0 = warp * 32;
    if (r0 >= N_NODES) return;
    int rend = r0 + 32; if (rend > N_NODES) rend = N_NODES;
    int curg = -1, cnt = 0;
    float p0 = 0.f, p1 = 0.f, p2 = 0.f, p3 = 0.f;
    for (int r = r0; r < rend; r++) {
        int g = load_idx(batch, r);
        float4 v = ((const float4*)d_bufB)[(size_t)r * 32 + lane];
        if (g != curg) {
            if (curg >= 0) {
                float* pp = &d_pooled[curg * HID + lane * 4];
                atomicAdd(pp + 0, p0); atomicAdd(pp + 1, p1);
                atomicAdd(pp + 2, p2); atomicAdd(pp + 3, p3);
                if (lane == 0) atomicAdd(&d_cnt[curg], (float)cnt);
            }
            curg = g; cnt = 1; p0 = v.x; p1 = v.y; p2 = v.z; p3 = v.w;
        } else { p0 += v.x; p1 += v.y; p2 += v.z; p3 += v.w; cnt++; }
    }
    if (curg >= 0) {
        float* pp = &d_pooled[curg * HID + lane * 4];
        atomicAdd(pp + 0, p0); atomicAdd(pp + 1, p1);
        atomicAdd(pp + 2, p2); atomicAdd(pp + 3, p3);
        if (lane == 0) atomicAdd(&d_cnt[curg], (float)cnt);
    }
}

__global__ void cls_kernel(const float* __restrict__ Wc, const float* __restrict__ bc,
                           float* __restrict__ out) {
    int g = blockIdx.x;
    int o = threadIdx.x >> 5, lane = threadIdx.x & 31;
    if (o >= OUTD) return;
    float inv = 1.0f / fmaxf(d_cnt[g], 1.0f);
    float s = 0.0f;
    for (int k = lane; k < HID; k += 32)
        s += d_pooled[g * HID + k] * Wc[k * OUTD + o];
    s = warp_sum(s);
    if (lane == 0) out[g * OUTD + o] = s * inv + bc[o];
}

extern "C" void kernel_launch(void* const* d_in, const int* in_sizes, int n_in,
                              void* d_out, int out_size) {
    const float* x      = (const float*)d_in[0];
    const void*  ei     = d_in[1];
    const void*  batch  = d_in[2];
    const float* W_rel  = (const float*)d_in[3];
    const float* b_rel  = (const float*)d_in[4];
    const float* W_root = (const float*)d_in[5];
    const float* gamma  = (const float*)d_in[6];
    const float* beta   = (const float*)d_in[7];
    const float* Wc     = (const float*)d_in[8];
    const float* bc     = (const float*)d_in[9];
    float* out = (float*)d_out;

    cudaFuncSetAttribute(layer_tc, cudaFuncAttributeMaxDynamicSharedMemorySize, SMEM_TOTAL);

    detect_kernel<<<1, 256>>>(ei);
    zero_kernel<<<(N_NODES + 255) / 256, 256>>>();
    transpose_w<<<256, 256>>>(W_rel, W_root);
    count_kernel<<<(N_EDGES + 255) / 256, 256>>>(ei);
    scan1_kernel<<<SCAN_BLOCKS, 1024>>>();
    scan2_kernel<<<1, 64>>>();
    scan3_kernel<<<SCAN_BLOCKS, 1024>>>();
    fill_kernel<<<(N_EDGES + 255) / 256, 256>>>(ei);

    int ntiles = (N_NODES + 127) / 128;
    // layer 0: x -> bufA
    aggregate_kernel<<<N_NODES / 8, 256>>>(x);
    layer_tc<<<ntiles, 256, SMEM_TOTAL>>>(x, b_rel, gamma, beta, 0, 0);
    // layer 1: bufA -> bufB
    aggregate_kernel<<<N_NODES / 8, 256>>>(nullptr);
    layer_tc<<<ntiles, 256, SMEM_TOTAL>>>(nullptr, b_rel + HID, gamma + HID, beta + HID, 1, 1);

    pool_kernel<<<196, 256>>>(batch);
    cls_kernel<<<NG, 320>>>(Wc, bc, out);
}

// round 11
// speedup vs baseline: 3.3334x; 1.0094x over previous
#include <cuda_runtime.h>
#include <cuda_bf16.h>
#include <cstdint>

#define N_NODES 50000
#define N_EDGES 800000
#define HID 128
#define NG 128
#define OUTD 10
#define EPS 1e-5f
#define SCAN_BLOCKS 49

#if defined(__CUDA_ARCH_FEAT_SM103_ALL) || defined(__CUDA_ARCH_FEAT_SM100_ALL) || \
    (defined(__CUDA_ARCH_SPECIFIC__))
#define HAS_TCGEN05 1
#else
#define HAS_TCGEN05 0
#endif

// ---- layer_tc smem layout (byte offsets from 1024-aligned base) ----
#define OFF_TMEM 0
#define OFF_MBAR0 8
#define OFF_MBAR1 16
#define OFF_BIAS 64
#define OFF_GAM  576
#define OFF_BET  1088
#define OFF_WH   2048                  // weight hi tile, blocked-atom, 32KB
#define OFF_WL   (OFF_WH + 32768)      // weight lo tile, 32KB
#define SMEM_USED (OFF_WH + 67584)     // staging (128*33*16B) overlays WH/WL
#define SMEM_TOTAL (SMEM_USED + 1024)  // + alignment slack  (~69.6KB; x2 CTAs fits)
// kind::f16 idesc, N=64 (proven encodings: test_mma M=128 cg1 f16; test_2cta N-field)
#define BF16_IDESC_N64 0x8100490u
#define TMEM_COLS 256                  // 2 CTAs x 256 = 512 = SM TMEM capacity
#define TM_D  0
#define TM_AH 128
#define TM_AL 192

// -------- device scratch --------
__device__ int   d_is64;
__device__ int   d_deg[N_NODES];
__device__ int   d_rowptr[N_NODES + 1];
__device__ int   d_cursor[N_NODES];
__device__ int   d_bsum[SCAN_BLOCKS];
__device__ int   d_btop[SCAN_BLOCKS];
__device__ int   d_col[N_EDGES];
__device__ __align__(16) float d_wt[4 * HID * HID];   // transposed weights [N][K]
__device__ __align__(16) float d_agg[N_NODES * HID];
__device__ __align__(16) float d_bufA[N_NODES * HID];
__device__ __align__(16) float d_bufB[N_NODES * HID];
__device__ __align__(16) float d_pooled[NG * HID];
__device__ float d_cnt[NG];

__device__ __forceinline__ float warp_sum(float v) {
    #pragma unroll
    for (int o = 16; o > 0; o >>= 1) v += __shfl_xor_sync(0xFFFFFFFFu, v, o);
    return v;
}
__device__ __forceinline__ int load_idx(const void* p, long long i) {
    if (d_is64) return (int)((const long long*)p)[i];
    return ((const int*)p)[i];
}
__device__ __forceinline__ uint32_t smem_u32(const void* p) {
    uint32_t a;
    asm("{ .reg .u64 t; cvta.to.shared.u64 t, %1; cvt.u32.u64 %0, t; }" : "=r"(a) : "l"(p));
    return a;
}
__device__ __forceinline__ uint64_t make_desc(uint32_t addr) {
    const uint64_t base = (uint64_t(2) << 61) | (uint64_t(1) << 46) |
                          (uint64_t(64) << 32) | (uint64_t(1) << 16);
    return base | ((uint64_t)(addr >> 4) & 0x3FFF);
}

#if HAS_TCGEN05
__device__ __forceinline__ uint32_t elect_one() {
    uint32_t r;
    asm volatile("{\n\t.reg .pred p;\n\telect.sync _|p, 0xFFFFFFFF;\n\tselp.b32 %0, 1, 0, p;\n\t}" : "=r"(r));
    return r;
}
#define TC_MMA_F16_TS(d_tmem, a_tmem, b_desc, idesc, enable_d) do { \
    uint32_t _enable = (enable_d) ? 1 : 0; \
    uint32_t _zero = 0; \
    asm volatile( \
        "{\n\t" \
        ".reg .pred p;\n\t" \
        "setp.ne.u32 p, %6, 0;\n\t" \
        "tcgen05.mma.cta_group::1.kind::f16 [%0], [%1], %2, %3, " \
        "{%4, %4, %4, %4}, p;\n\t" \
        "}" \
        :: "r"(d_tmem), "r"(a_tmem), "l"(b_desc), "r"(idesc), \
           "r"(_zero), "r"(_zero), "r"(_enable) \
        : "memory"); \
} while (0)
#define TC_ALLOC(slot, n)   asm volatile("tcgen05.alloc.cta_group::1.sync.aligned.shared::cta.b32 [%0], %1;" :: "r"(slot), "r"((uint32_t)(n)) : "memory")
#define TC_DEALLOC(t, n)    asm volatile("tcgen05.dealloc.cta_group::1.sync.aligned.b32 %0, %1;" :: "r"(t), "r"((uint32_t)(n)))
#define TC_COMMIT(mb)       asm volatile("tcgen05.commit.cta_group::1.mbarrier::arrive::one.shared::cluster.b64 [%0];" :: "r"(mb) : "memory")
#define TC_WAIT_LD()        asm volatile("tcgen05.wait::ld.sync.aligned;" ::: "memory")
#define TC_WAIT_ST()        asm volatile("tcgen05.wait::st.sync.aligned;" ::: "memory")
#define TC_FENCE_AFTER()    asm volatile("tcgen05.fence::after_thread_sync;" ::: "memory")
#define TC_FENCE_BEFORE()   asm volatile("tcgen05.fence::before_thread_sync;" ::: "memory")
#define MBAR_INIT(mb, c)    asm volatile("mbarrier.init.shared.b64 [%0], %1;" :: "r"(mb), "r"((uint32_t)(c)) : "memory")
#define MBAR_INVAL(mb)      asm volatile("mbarrier.inval.shared.b64 [%0];" :: "r"(mb) : "memory")
#define MBAR_WAIT(mb, ph) do { \
    uint32_t _m = (mb), _p = (ph), _d; \
    asm volatile("{\n\t.reg .pred p;\n\tmbarrier.try_wait.parity.acquire.cta.shared::cta.b64 p, [%1], %2;\n\tselp.b32 %0, 1, 0, p;\n\t}" \
        : "=r"(_d) : "r"(_m), "r"(_p) : "memory"); \
    if (!_d) { \
        asm volatile("{\n\t.reg .pred P1;\n\tWL_%=:\n\tmbarrier.try_wait.parity.acquire.cta.shared::cta.b64 P1, [%0], %1, 0x989680;\n\t@P1 bra.uni WD_%=;\n\tbra.uni WL_%=;\n\tWD_%=:\n\t}" \
            :: "r"(_m), "r"(_p) : "memory"); \
    } \
} while (0)

#define TC_ST_X16(tmem_addr, r) \
    asm volatile( \
        "tcgen05.st.sync.aligned.32x32b.x16.b32 [%0], " \
        "{%1, %2, %3, %4, %5, %6, %7, %8, " \
        " %9, %10, %11, %12, %13, %14, %15, %16};" \
        :: "r"(tmem_addr), \
           "r"((r)[0]),  "r"((r)[1]),  "r"((r)[2]),  "r"((r)[3]), \
           "r"((r)[4]),  "r"((r)[5]),  "r"((r)[6]),  "r"((r)[7]), \
           "r"((r)[8]),  "r"((r)[9]),  "r"((r)[10]), "r"((r)[11]), \
           "r"((r)[12]), "r"((r)[13]), "r"((r)[14]), "r"((r)[15]) \
        : "memory")

#define TC_LD_X32(r, addr) \
    asm volatile( \
        "tcgen05.ld.sync.aligned.32x32b.x32.b32 " \
        "{%0, %1, %2, %3, %4, %5, %6, %7, %8, %9, %10, %11, %12, %13, %14, %15, " \
        " %16, %17, %18, %19, %20, %21, %22, %23, %24, %25, %26, %27, %28, %29, %30, %31}, [%32];" \
        : "=r"((r)[0]), "=r"((r)[1]), "=r"((r)[2]), "=r"((r)[3]), \
          "=r"((r)[4]), "=r"((r)[5]), "=r"((r)[6]), "=r"((r)[7]), \
          "=r"((r)[8]), "=r"((r)[9]), "=r"((r)[10]), "=r"((r)[11]), \
          "=r"((r)[12]), "=r"((r)[13]), "=r"((r)[14]), "=r"((r)[15]), \
          "=r"((r)[16]), "=r"((r)[17]), "=r"((r)[18]), "=r"((r)[19]), \
          "=r"((r)[20]), "=r"((r)[21]), "=r"((r)[22]), "=r"((r)[23]), \
          "=r"((r)[24]), "=r"((r)[25]), "=r"((r)[26]), "=r"((r)[27]), \
          "=r"((r)[28]), "=r"((r)[29]), "=r"((r)[30]), "=r"((r)[31]) \
        : "r"(addr))
#endif  // HAS_TCGEN05

// -------- prep: detect dtype + zero accumulators + transpose weights --------
// block 0: detect; blocks 1..196: zero; blocks 197..452: transpose
__global__ void prep_kernel(const void* ei, const float* __restrict__ W_rel,
                            const float* __restrict__ W_root) {
    int bid = blockIdx.x, tid = threadIdx.x;
    if (bid == 0) {
        __shared__ int bad;
        if (tid == 0) bad = 0;
        __syncthreads();
        long long v = ((const long long*)ei)[tid];
        if (v < 0 || v >= N_NODES) bad = 1;
        __syncthreads();
        if (tid == 0) d_is64 = !bad;
    } else if (bid <= 196) {
        int i = (bid - 1) * 256 + tid;
        if (i < N_NODES) d_deg[i] = 0;
        if (i < NG * HID) d_pooled[i] = 0.0f;
        if (i < NG) d_cnt[i] = 0.0f;
    } else {
        int idx = (bid - 197) * 256 + tid;        // 0..65535
        int m = idx >> 14, e = idx & 16383;
        int n = e >> 7, k = e & 127;
        const float* src = (m & 1) ? (W_root + (m >> 1) * HID * HID)
                                   : (W_rel  + (m >> 1) * HID * HID);
        d_wt[m * HID * HID + n * HID + k] = src[k * HID + n];
    }
}

// -------- CSR build (2 edges per thread) --------
__global__ void count_kernel(const void* __restrict__ ei) {
    int e0 = (blockIdx.x * blockDim.x + threadIdx.x) * 2;
    if (e0 < N_EDGES) {
        atomicAdd(&d_deg[load_idx(ei, (long long)N_EDGES + e0)], 1);
        if (e0 + 1 < N_EDGES)
            atomicAdd(&d_deg[load_idx(ei, (long long)N_EDGES + e0 + 1)], 1);
    }
}
__global__ void scan1_kernel() {
    __shared__ int sh[1024];
    int tid = threadIdx.x, i = blockIdx.x * 1024 + tid;
    int v = (i < N_NODES) ? d_deg[i] : 0;
    sh[tid] = v; __syncthreads();
    #pragma unroll
    for (int s = 1; s < 1024; s <<= 1) {
        int t = (tid >= s) ? sh[tid - s] : 0;
        __syncthreads(); sh[tid] += t; __syncthreads();
    }
    if (i < N_NODES) d_rowptr[i] = sh[tid] - v;
    if (tid == 1023) d_bsum[blockIdx.x] = sh[1023];
}
__global__ void scan2_kernel() {
    __shared__ int sh[64];
    int tid = threadIdx.x;
    int v = (tid < SCAN_BLOCKS) ? d_bsum[tid] : 0;
    sh[tid] = v; __syncthreads();
    #pragma unroll
    for (int s = 1; s < 64; s <<= 1) {
        int t = (tid >= s) ? sh[tid - s] : 0;
        __syncthreads(); sh[tid] += t; __syncthreads();
    }
    if (tid < SCAN_BLOCKS) d_btop[tid] = sh[tid] - v;
}
__global__ void scan3_kernel() {
    int i = blockIdx.x * blockDim.x + threadIdx.x;
    if (i < N_NODES) {
        int r = d_rowptr[i] + d_btop[i >> 10];
        d_rowptr[i] = r; d_cursor[i] = r;
    }
    if (i == 0) d_rowptr[N_NODES] = N_EDGES;
}
__global__ void fill_kernel(const void* __restrict__ ei) {
    int e0 = (blockIdx.x * blockDim.x + threadIdx.x) * 2;
    #pragma unroll
    for (int j = 0; j < 2; j++) {
        int e = e0 + j;
        if (e < N_EDGES) {
            int src = load_idx(ei, e);
            int dst = load_idx(ei, (long long)N_EDGES + e);
            d_col[atomicAdd(&d_cursor[dst], 1)] = src;
        }
    }
}

// -------- mean aggregation: warp/node, 2-way unrolled gather --------
__global__ void aggregate_kernel(const float* __restrict__ xsrc) {
    const float* xp = xsrc ? xsrc : d_bufA;
    int gw = (blockIdx.x * blockDim.x + threadIdx.x) >> 5;
    int lane = threadIdx.x & 31;
    if (gw >= N_NODES) return;
    int b = d_rowptr[gw], e = d_rowptr[gw + 1];
    float4 a0 = make_float4(0.f, 0.f, 0.f, 0.f);
    float4 a1 = make_float4(0.f, 0.f, 0.f, 0.f);
    const float4* x4 = (const float4*)xp;
    int i = b;
    for (; i + 2 <= e; i += 2) {
        int s0 = __ldg(&d_col[i]);
        int s1 = __ldg(&d_col[i + 1]);
        float4 v0 = __ldg(&x4[(size_t)s0 * 32 + lane]);
        float4 v1 = __ldg(&x4[(size_t)s1 * 32 + lane]);
        a0.x += v0.x; a0.y += v0.y; a0.z += v0.z; a0.w += v0.w;
        a1.x += v1.x; a1.y += v1.y; a1.z += v1.z; a1.w += v1.w;
    }
    if (i < e) {
        int s0 = __ldg(&d_col[i]);
        float4 v0 = __ldg(&x4[(size_t)s0 * 32 + lane]);
        a0.x += v0.x; a0.y += v0.y; a0.z += v0.z; a0.w += v0.w;
    }
    float inv = (e > b) ? 1.0f / (float)(e - b) : 0.0f;
    a0.x = (a0.x + a1.x) * inv; a0.y = (a0.y + a1.y) * inv;
    a0.z = (a0.z + a1.z) * inv; a0.w = (a0.w + a1.w) * inv;
    ((float4*)d_agg)[(size_t)gw * 32 + lane] = a0;
}

#if HAS_TCGEN05
// -------- split f32 -> hi/lo bf16x2 words --------
__device__ __forceinline__ void split4(float4 v, uint32_t* hw, uint32_t* lw) {
    __nv_bfloat16 h0 = __float2bfloat16(v.x), h1 = __float2bfloat16(v.y);
    __nv_bfloat16 h2 = __float2bfloat16(v.z), h3 = __float2bfloat16(v.w);
    __nv_bfloat16 l0 = __float2bfloat16(v.x - __bfloat162float(h0));
    __nv_bfloat16 l1 = __float2bfloat16(v.y - __bfloat162float(h1));
    __nv_bfloat16 l2 = __float2bfloat16(v.z - __bfloat162float(h2));
    __nv_bfloat16 l3 = __float2bfloat16(v.w - __bfloat162float(h3));
    __nv_bfloat162 hp0 = __halves2bfloat162(h0, h1), hp1 = __halves2bfloat162(h2, h3);
    __nv_bfloat162 lp0 = __halves2bfloat162(l0, l1), lp1 = __halves2bfloat162(l2, l3);
    hw[0] = *(uint32_t*)&hp0; hw[1] = *(uint32_t*)&hp1;
    lw[0] = *(uint32_t*)&lp0; lw[1] = *(uint32_t*)&lp1;
}

__device__ __forceinline__ void store_A_tmem(uint32_t tmem, const float* gsrc, int row0) {
    int tid = threadIdx.x;
    if (tid >= 128) return;
    int gr = row0 + tid;
    bool ok = gr < N_NODES;
    const float4* rp = (const float4*)gsrc + (size_t)gr * 32;
    uint32_t woff = ((uint32_t)(tid >> 5)) << 21;
    #pragma unroll
    for (int ch = 0; ch < 4; ch++) {      // 16 TMEM cols (= 32 f32) per chunk
        uint32_t hw[16], lw[16];
        #pragma unroll
        for (int q = 0; q < 8; q++) {
            float4 v = ok ? __ldg(rp + ch * 8 + q) : make_float4(0.f, 0.f, 0.f, 0.f);
            split4(v, hw + q * 2, lw + q * 2);
        }
        TC_ST_X16(tmem + TM_AH + ch * 16 + woff, hw);
        TC_ST_X16(tmem + TM_AL + ch * 16 + woff, lw);
    }
    TC_WAIT_ST();
}

// atom = 8 rows x 64 bf16 (1024B); tiling (16 atom-rows, 2 atom-cols), stride (1,16).
__device__ __forceinline__ void store_W_smem(char* base, const float* wt) {
    int tid = threadIdx.x;
    #pragma unroll
    for (int i = 0; i < 8; i++) {
        int chunk = tid + i * 256;        // 0..2047, each = 8 bf16 (16B)
        int n = chunk >> 4, c8 = chunk & 15;
        const float4* p = (const float4*)(wt + n * HID + c8 * 8);
        float4 v0 = __ldg(p), v1 = __ldg(p + 1);
        uint32_t hw[4], lw[4];
        split4(v0, hw, lw);
        split4(v1, hw + 2, lw + 2);
        int atom_row = n >> 3, inner_row = n & 7;
        int atom_col = c8 >> 3, ic8 = c8 & 7;
        uint32_t b = (uint32_t)((atom_row + atom_col * 16) * 1024 + inner_row * 128 + ic8 * 16);
        b ^= (b >> 3) & 0x70;             // SW128
        *(uint4*)(base + OFF_WH + b) = make_uint4(hw[0], hw[1], hw[2], hw[3]);
        *(uint4*)(base + OFF_WL + b) = make_uint4(lw[0], lw[1], lw[2], lw[3]);
    }
}

// 48 MMAs: 2 N-halves x (Ah,Bh),(Ah,Bl),(Al,Bh) x 8 K-steps (K=16 each).
__device__ __forceinline__ void mma_gemm_ts(uint32_t tmem, uint32_t sbase, bool first) {
    uint64_t bh = make_desc(sbase + OFF_WH);
    uint64_t bl = make_desc(sbase + OFF_WL);
    uint32_t ah = tmem + TM_AH, al = tmem + TM_AL;
    uint32_t apair[3] = {ah, ah, al};
    uint64_t bpair[3] = {bh, bl, bh};
    #pragma unroll
    for (int h = 0; h < 2; h++) {
        #pragma unroll
        for (int p = 0; p < 3; p++) {
            #pragma unroll
            for (int s = 0; s < 8; s++) {
                uint64_t bd = bpair[p] + (uint64_t)(h * 512 + (s >> 2) * 1024 + (s & 3) * 2);
                TC_MMA_F16_TS(tmem + TM_D + h * 64, apair[p] + s * 8, bd, BF16_IDESC_N64,
                              !(first && p == 0 && s == 0));
            }
        }
    }
}
#endif

// -------- layer: out = relu(LN(agg@Wrel + brel + x@Wroot)) --------
// Weights come from the d_wt device symbol selected by `layer` inside device
// code (host-side &d_wt is the HOST shadow; GB300 ATS reads zeros — rounds-4..9 bug).
__global__ void __launch_bounds__(256, 2) __cluster_dims__(1, 1, 1) layer_tc(
    const float* __restrict__ xin,        // nullptr -> d_bufA
    const float* __restrict__ brel,
    const float* __restrict__ gam,
    const float* __restrict__ bet,
    int layer, int outsel)
{
    extern __shared__ char smem_raw[];
    const float* xp = xin ? xin : d_bufA;
    float* outp = outsel ? d_bufB : d_bufA;
    const float* wtrel  = d_wt + (2 * layer)     * HID * HID;
    const float* wtroot = d_wt + (2 * layer + 1) * HID * HID;
    int tid = threadIdx.x;
    int row0 = blockIdx.x * 128;

#if HAS_TCGEN05
    uint32_t sraw = smem_u32(smem_raw);
    uint32_t sbase = (sraw + 1023u) & ~1023u;   // SW128 tiles need 1024B alignment
    char* base = smem_raw + (sbase - sraw);
    int wid = tid >> 5;

    float* sBias = (float*)(base + OFF_BIAS);
    float* sGam  = (float*)(base + OFF_GAM);
    float* sBet  = (float*)(base + OFF_BET);
    if (tid < 128) { sBias[tid] = brel[tid]; sGam[tid] = gam[tid]; sBet[tid] = bet[tid]; }

    // alloc by warp 0 ONLY; no relinquish (hi-wid-first arbiter trap).
    if (wid == 0) { TC_ALLOC(sbase + OFF_TMEM, TMEM_COLS); }
    if (tid == 0) { MBAR_INIT(sbase + OFF_MBAR0, 1); MBAR_INIT(sbase + OFF_MBAR1, 1); }
    __syncthreads();
    uint32_t tmem;
    asm volatile("ld.shared.b32 %0, [%1];" : "=r"(tmem) : "r"(sbase + OFF_TMEM));

    // ---- GEMM 1: D = agg @ Wrel^T ----
    store_A_tmem(tmem, d_agg, row0);
    store_W_smem(base, wtrel);
    TC_FENCE_BEFORE();
    __syncthreads();
    if (wid == 0) {
        TC_FENCE_AFTER();
        if (elect_one()) {
            mma_gemm_ts(tmem, sbase, true);
            TC_COMMIT(sbase + OFF_MBAR0);
        }
    }
    MBAR_WAIT(sbase + OFF_MBAR0, 0);

    // ---- GEMM 2: D += x @ Wroot^T ----
    store_A_tmem(tmem, xp, row0);
    store_W_smem(base, wtroot);
    TC_FENCE_BEFORE();
    __syncthreads();
    if (wid == 0) {
        TC_FENCE_AFTER();
        if (elect_one()) {
            mma_gemm_ts(tmem, sbase, false);
            TC_COMMIT(sbase + OFF_MBAR1);
        }
    }
    MBAR_WAIT(sbase + OFF_MBAR1, 0);
    TC_FENCE_AFTER();

    // ---- epilogue (register-lean, 2-pass): thread = row ----
    // pass 1: sum & sumsq over 32-col chunks; pass 2: re-read, normalize, stage.
    float* stg = (float*)(base + OFF_WH);   // stride 132 floats (33 float4)
    if (tid < 128) {
        float sum = 0.0f, sq = 0.0f;
        #pragma unroll
        for (int ch = 0; ch < 4; ch++) {
            uint32_t t[32];
            TC_LD_X32(t, tmem + TM_D + ch * 32);
            TC_WAIT_LD();
            #pragma unroll
            for (int c = 0; c < 32; c++) {
                float v = __uint_as_float(t[c]) + sBias[ch * 32 + c];
                sum += v;
                sq += v * v;
            }
        }
        float mu = sum * (1.0f / 128.0f);
        float var = sq * (1.0f / 128.0f) - mu * mu;
        float rs = rsqrtf(fmaxf(var, 0.0f) + EPS);
        int r = tid;
        #pragma unroll
        for (int ch = 0; ch < 4; ch++) {
            uint32_t t[32];
            TC_LD_X32(t, tmem + TM_D + ch * 32);
            TC_WAIT_LD();
            #pragma unroll
            for (int c4 = 0; c4 < 8; c4++) {
                float4 ov;
                float* o = (float*)&ov;
                #pragma unroll
                for (int j = 0; j < 4; j++) {
                    int cc = c4 * 4 + j;
                    int c = ch * 32 + cc;
                    float v = __uint_as_float(t[cc]) + sBias[c];
                    o[j] = fmaxf(sGam[c] * (v - mu) * rs + sBet[c], 0.0f);
                }
                ((float4*)stg)[r * 33 + ch * 8 + c4] = ov;
            }
        }
        TC_FENCE_BEFORE();
    }
    __syncthreads();

    #pragma unroll
    for (int i = 0; i < 16; i++) {
        int idx = tid + i * 256;
        int r = idx >> 5, c4 = idx & 31;
        int gr = row0 + r;
        if (gr < N_NODES)
            ((float4*)outp)[(size_t)gr * 32 + c4] = ((float4*)stg)[r * 33 + c4];
    }
    __syncthreads();

    if (tid == 0) { MBAR_INVAL(sbase + OFF_MBAR0); MBAR_INVAL(sbase + OFF_MBAR1); }
    __syncthreads();
    if (wid == 0) { TC_DEALLOC(tmem, TMEM_COLS); }

#else
    // ---- SIMT fallback (generic sm_103 pass only) ----
    char* smem = smem_raw;
    float (*As)[132] = (float(*)[132])(smem);
    float (*Bs)[128] = (float(*)[128])(smem + 32 * 132 * 4);
    int lane = tid & 31;
    int w = tid >> 5;
    int w16 = w * 16;

    float acc[16][4];
    #pragma unroll
    for (int r = 0; r < 16; r++)
        #pragma unroll
        for (int j = 0; j < 4; j++) acc[r][j] = 0.0f;

    #pragma unroll
    for (int pass = 0; pass < 2; pass++) {
        const float* A = pass ? xp : d_agg;
        const float* Wt = pass ? wtroot : wtrel;
        #pragma unroll
        for (int k0 = 0; k0 < 128; k0 += 32) {
            __syncthreads();
            #pragma unroll
            for (int i = 0; i < 16; i++) {
                int r = w + i * 8;
                int gr = row0 + r;
                As[lane][r] = (gr < N_NODES) ? A[(size_t)gr * HID + k0 + lane] : 0.0f;
            }
            #pragma unroll
            for (int i = 0; i < 16; i++) {
                int idx = tid + i * 256;
                int kk = idx >> 7, nn = idx & 127;
                Bs[kk][nn] = Wt[(size_t)nn * HID + k0 + kk];
            }
            __syncthreads();
            #pragma unroll
            for (int kc = 0; kc < 32; kc++) {
                float4 b4 = *(const float4*)&Bs[kc][lane * 4];
                float ar[16];
                *(float4*)&ar[0]  = *(const float4*)&As[kc][w16];
                *(float4*)&ar[4]  = *(const float4*)&As[kc][w16 + 4];
                *(float4*)&ar[8]  = *(const float4*)&As[kc][w16 + 8];
                *(float4*)&ar[12] = *(const float4*)&As[kc][w16 + 12];
                #pragma unroll
                for (int r = 0; r < 16; r++) {
                    acc[r][0] += ar[r] * b4.x;
                    acc[r][1] += ar[r] * b4.y;
                    acc[r][2] += ar[r] * b4.z;
                    acc[r][3] += ar[r] * b4.w;
                }
            }
        }
    }

    int c0 = lane * 4;
    float4 bb = *(const float4*)&brel[c0];
    float4 gg = *(const float4*)&gam[c0];
    float4 be = *(const float4*)&bet[c0];
    #pragma unroll
    for (int r = 0; r < 16; r++) {
        int gr = row0 + w16 + r;
        if (gr >= N_NODES) break;
        float v0 = acc[r][0] + bb.x, v1 = acc[r][1] + bb.y;
        float v2 = acc[r][2] + bb.z, v3 = acc[r][3] + bb.w;
        float mu = warp_sum(v0 + v1 + v2 + v3) * (1.0f / 128.0f);
        float d0 = v0 - mu, d1 = v1 - mu, d2 = v2 - mu, d3 = v3 - mu;
        float var = warp_sum(d0 * d0 + d1 * d1 + d2 * d2 + d3 * d3) * (1.0f / 128.0f);
        float rs = rsqrtf(var + EPS);
        float4 ov;
        ov.x = fmaxf(gg.x * d0 * rs + be.x, 0.0f);
        ov.y = fmaxf(gg.y * d1 * rs + be.y, 0.0f);
        ov.z = fmaxf(gg.z * d2 * rs + be.z, 0.0f);
        ov.w = fmaxf(gg.w * d3 * rs + be.w, 0.0f);
        *(float4*)&outp[(size_t)gr * HID + c0] = ov;
    }
#endif
}

// -------- graph mean pooling: warp handles 32 consecutive rows, run-length --------
__global__ void pool_kernel(const void* __restrict__ batch) {
    int warp = (blockIdx.x * blockDim.x + threadIdx.x) >> 5;
    int lane = threadIdx.x & 31;
    int r0 = warp * 32;
    if (r0 >= N_NODES) return;
    int rend = r0 + 32; if (rend > N_NODES) rend = N_NODES;
    int curg = -1, cnt = 0;
    float p0 = 0.f, p1 = 0.f, p2 = 0.f, p3 = 0.f;
    for (int r = r0; r < rend; r++) {
        int g = load_idx(batch, r);
        float4 v = ((const float4*)d_bufB)[(size_t)r * 32 + lane];
        if (g != curg) {
            if (curg >= 0) {
                float* pp = &d_pooled[curg * HID + lane * 4];
                atomicAdd(pp + 0, p0); atomicAdd(pp + 1, p1);
                atomicAdd(pp + 2, p2); atomicAdd(pp + 3, p3);
                if (lane == 0) atomicAdd(&d_cnt[curg], (float)cnt);
            }
            curg = g; cnt = 1; p0 = v.x; p1 = v.y; p2 = v.z; p3 = v.w;
        } else { p0 += v.x; p1 += v.y; p2 += v.z; p3 += v.w; cnt++; }
    }
    if (curg >= 0) {
        float* pp = &d_pooled[curg * HID + lane * 4];
        atomicAdd(pp + 0, p0); atomicAdd(pp + 1, p1);
        atomicAdd(pp + 2, p2); atomicAdd(pp + 3, p3);
        if (lane == 0) atomicAdd(&d_cnt[curg], (float)cnt);
    }
}

__global__ void cls_kernel(const float* __restrict__ Wc, const float* __restrict__ bc,
                           float* __restrict__ out) {
    int g = blockIdx.x;
    int o = threadIdx.x >> 5, lane = threadIdx.x & 31;
    if (o >= OUTD) return;
    float inv = 1.0f / fmaxf(d_cnt[g], 1.0f);
    float s = 0.0f;
    for (int k = lane; k < HID; k += 32)
        s += d_pooled[g * HID + k] * Wc[k * OUTD + o];
    s = warp_sum(s);
    if (lane == 0) out[g * OUTD + o] = s * inv + bc[o];
}

extern "C" void kernel_launch(void* const* d_in, const int* in_sizes, int n_in,
                              void* d_out, int out_size) {
    const float* x      = (const float*)d_in[0];
    const void*  ei     = d_in[1];
    const void*  batch  = d_in[2];
    const float* W_rel  = (const float*)d_in[3];
    const float* b_rel  = (const float*)d_in[4];
    const float* W_root = (const float*)d_in[5];
    const float* gamma  = (const float*)d_in[6];
    const float* beta   = (const float*)d_in[7];
    const float* Wc     = (const float*)d_in[8];
    const float* bc     = (const float*)d_in[9];
    float* out = (float*)d_out;

    cudaFuncSetAttribute(layer_tc, cudaFuncAttributeMaxDynamicSharedMemorySize, SMEM_TOTAL);

    prep_kernel<<<453, 256>>>(ei, W_rel, W_root);
    count_kernel<<<(N_EDGES / 2 + 255) / 256, 256>>>(ei);
    scan1_kernel<<<SCAN_BLOCKS, 1024>>>();
    scan2_kernel<<<1, 64>>>();
    scan3_kernel<<<SCAN_BLOCKS, 1024>>>();
    fill_kernel<<<(N_EDGES / 2 + 255) / 256, 256>>>(ei);

    int ntiles = (N_NODES + 127) / 128;
    // layer 0: x -> bufA
    aggregate_kernel<<<N_NODES / 8, 256>>>(x);
    layer_tc<<<ntiles, 256, SMEM_TOTAL>>>(x, b_rel, gamma, beta, 0, 0);
    // layer 1: bufA -> bufB
    aggregate_kernel<<<N_NODES / 8, 256>>>(nullptr);
    layer_tc<<<ntiles, 256, SMEM_TOTAL>>>(nullptr, b_rel + HID, gamma + HID, beta + HID, 1, 1);

    pool_kernel<<<196, 256>>>(batch);
    cls_kernel<<<NG, 320>>>(Wc, bc, out);
}